// round 3
// baseline (speedup 1.0000x reference)
#include <cuda_runtime.h>
#include <cstdint>

// Problem constants
#define BATCH    16384
#define IN_SIZE  448
#define OUT_SIZE 448
#define W_TOT    14336
#define NE       64
#define NB       64          // nodes per compute tile
#define NTHREADS 256         // compute kernel
#define PTHREADS 128         // preproc kernels
#define NHB      (BATCH / PTHREADS)   // 128 preproc blocks
#define MAX_TILES 384
#define GRID_COMPUTE 296     // 2 CTAs/SM x 148 SMs

// Device scratch (allocation-free rule)
__device__ int g_hist[NHB][NE];
__device__ int g_base[NHB][NE];
__device__ int g_offset[NE + 1];
__device__ int g_perm[BATCH];
__device__ int g_ntiles;
__device__ int g_tile_ctr;
__device__ int g_tile_e[MAX_TILES];
__device__ int g_tile_r0[MAX_TILES];
__device__ int g_tile_R[MAX_TILES];

__device__ __forceinline__ int get_idx(const void* p, int b, int is64) {
    if (is64) return (int)((const long long*)p)[b];
    return ((const int*)p)[b];
}

// Block-cooperative dtype detection. If data were int32 in [0,64), the 32
// sampled int64 reinterpretations are all in [0,64) only if all odd int32s
// are 0: probability (1/64)^32 ~ 0.
__device__ __forceinline__ int detect_is64(const void* idxp, int tid, int* s_flag) {
    if (tid < 32) {
        long long v = ((const long long*)idxp)[tid];
        unsigned ok = __ballot_sync(0xFFFFFFFFu, v >= 0 && v < 64);
        if (tid == 0) *s_flag = (ok == 0xFFFFFFFFu) ? 1 : 0;
    }
    __syncthreads();
    return *s_flag;
}

// ---------------------------------------------------------------------------
// Pass 1: per-block histogram (no global atomics, no init kernel needed)
// ---------------------------------------------------------------------------
__global__ void hist_kernel(const void* idxp) {
    __shared__ int h[NE];
    __shared__ int sflag;
    int tid = threadIdx.x;
    if (tid < NE) h[tid] = 0;
    int is64 = detect_is64(idxp, tid, &sflag);  // contains __syncthreads
    int b = blockIdx.x * PTHREADS + tid;
    int e = get_idx(idxp, b, is64);
    atomicAdd(&h[e], 1);
    __syncthreads();
    if (tid < NE) g_hist[blockIdx.x][tid] = h[tid];
}

// ---------------------------------------------------------------------------
// Pass 2: scan + per-block scatter bases + bucket-aligned tile list
// ---------------------------------------------------------------------------
__global__ void scan_tiles_kernel() {
    __shared__ int cnt[NE];
    __shared__ int toff[NE];
    int e = threadIdx.x;          // 64 threads
    int s = 0;
    #pragma unroll 8
    for (int b = 0; b < NHB; b++) { g_base[b][e] = s; s += g_hist[b][e]; }
    cnt[e] = s;
    __syncthreads();
    if (e == 0) {
        int s2 = 0, ts = 0;
        for (int i = 0; i < NE; i++) {
            g_offset[i] = s2; s2 += cnt[i];
            toff[i] = ts; ts += (cnt[i] + NB - 1) / NB;
        }
        g_offset[NE] = s2;
        g_ntiles = ts;
        g_tile_ctr = 0;           // reset persistent counter every replay
    }
    __syncthreads();
    int off = g_offset[e];
    #pragma unroll 8
    for (int b = 0; b < NHB; b++) g_base[b][e] += off;
    int c = cnt[e], tb = toff[e];
    for (int i = 0; i * NB < c; i++) {
        g_tile_e[tb + i]  = e;
        g_tile_r0[tb + i] = off + i * NB;
        g_tile_R[tb + i]  = min(NB, c - i * NB);
    }
}

// ---------------------------------------------------------------------------
// Pass 3: scatter, zero global atomics (precomputed per-block bases)
// ---------------------------------------------------------------------------
__global__ void scatter_kernel(const void* idxp) {
    __shared__ int h[NE];
    __shared__ int sflag;
    int tid = threadIdx.x;
    if (tid < NE) h[tid] = 0;
    int is64 = detect_is64(idxp, tid, &sflag);
    int b = blockIdx.x * PTHREADS + tid;
    int e = get_idx(idxp, b, is64);
    int rank = atomicAdd(&h[e], 1);   // smem atomic only
    g_perm[g_base[blockIdx.x][e] + rank] = b;
}

// ---------------------------------------------------------------------------
// Compute: persistent, cp.async staging, register-tiled SIMT GEMM
// ---------------------------------------------------------------------------
#define ROW_PAD 4
#define XY_FLOATS (NB * (192 + ROW_PAD))
#define SMEM_FLOATS (W_TOT + XY_FLOATS)
#define SMEM_BYTES  (SMEM_FLOATS * 4)

__device__ __forceinline__ uint32_t smem_u32(const void* p) {
    uint32_t a;
    asm("{ .reg .u64 t; cvta.to.shared.u64 t, %1; cvt.u32.u64 %0, t; }"
        : "=r"(a) : "l"(p));
    return a;
}
__device__ __forceinline__ void cpa16(uint32_t dst, const void* src) {
    asm volatile("cp.async.cg.shared.global [%0], [%1], 16;\n" :: "r"(dst), "l"(src));
}
__device__ __forceinline__ void cpa_commit_wait() {
    asm volatile("cp.async.commit_group;\ncp.async.wait_group 0;\n" ::: "memory");
}

// Issue cp.async for x rows [0,R) of this segment; zero-fill rows [R, R+4)
// (only those can be touched by boundary threads' register tiles).
template<int LEN, int XOFF>
__device__ __forceinline__ void stage_x(
    uint32_t sXY_u, float* sXY, const float* __restrict__ x,
    const int* __restrict__ s_node, int R, int tid)
{
    constexpr int LEN4 = LEN / 4;
    constexpr int LENP = LEN + ROW_PAD;
    const int RZ = min(NB, R + 4);
    for (int idx = tid; idx < NB * LEN4; idx += NTHREADS) {
        int nb = idx / LEN4, o4 = idx - nb * LEN4;
        int soff = nb * LENP + 4 * o4;
        if (nb < R) {
            cpa16(sXY_u + 4u * soff,
                  x + (size_t)s_node[nb] * IN_SIZE + XOFF + 4 * o4);
        } else if (nb < RZ) {
            *(float4*)(sXY + soff) = make_float4(0.f, 0.f, 0.f, 0.f);
        }
    }
}

// Compute one segment (x already staged in sXY). Ends with __syncthreads().
template<int MI, int MO, int D, int TNX, int TN, int TNY, int TM,
         int WOFF, int YOFF>
__device__ __forceinline__ void seg_compute(
    const float* __restrict__ sW, float* __restrict__ sXY,
    float* __restrict__ y, const int* __restrict__ s_node, int R, int tid)
{
    constexpr int LEN   = MI * D;
    constexpr int OLEN  = MO * D;
    constexpr int LENP  = LEN + ROW_PAD;
    constexpr int OLENP = OLEN + ROW_PAD;
    constexpr int OLEN4 = OLEN / 4;
    static_assert(TNX * TNY == NTHREADS, "thread grid");
    static_assert(TNX * TN == MO, "col tiling");
    static_assert(TNY * TM == NB * D, "row tiling");

    const int tx = tid % TNX;
    const int ty = tid / TNX;
    // Rows are monotone in node: if this thread's first node >= R, all its
    // rows are zero-padding -> skip the FMA loop and y staging entirely.
    const bool active = ((ty * TM) / D) < R;

    float acc[TM][TN];
    int xbase[TM];
    #pragma unroll
    for (int a = 0; a < TM; a++) {
        int r = ty * TM + a;
        int nb = r / D, m = r - nb * D;
        xbase[a] = nb * LENP + m;
        #pragma unroll
        for (int j = 0; j < TN; j++) acc[a][j] = 0.f;
    }

    if (active) {
        #pragma unroll 2
        for (int k = 0; k < MI; k++) {
            float wv[TN];
            #pragma unroll
            for (int j = 0; j < TN; j++)
                wv[j] = sW[WOFF + k * MO + tx + TNX * j];
            #pragma unroll
            for (int a = 0; a < TM; a++) {
                float xv = sXY[xbase[a] + k * D];
                #pragma unroll
                for (int j = 0; j < TN; j++)
                    acc[a][j] = fmaf(xv, wv[j], acc[a][j]);
            }
        }
    }
    __syncthreads();   // all x reads done before overwrite with y

    if (active) {
        #pragma unroll
        for (int a = 0; a < TM; a++) {
            int r = ty * TM + a;
            int nb = r / D, m = r - nb * D;
            #pragma unroll
            for (int j = 0; j < TN; j++) {
                int o = tx + TNX * j;
                sXY[nb * OLENP + o * D + m] = acc[a][j];
            }
        }
    }
    __syncthreads();

    // Coalesced vectorized write-out (valid rows only)
    for (int idx = tid; idx < R * OLEN4; idx += NTHREADS) {
        int nb = idx / OLEN4, o4 = idx - nb * OLEN4;
        *(float4*)(y + (size_t)s_node[nb] * OUT_SIZE + YOFF + 4 * o4) =
            *(const float4*)(sXY + nb * OLENP + 4 * o4);
    }
    __syncthreads();   // sXY/sW reusable afterwards
}

__global__ void __launch_bounds__(NTHREADS)
compute_kernel(const float* __restrict__ W, const float* __restrict__ x,
               float* __restrict__ y)
{
    extern __shared__ float smem[];
    float* sW  = smem;
    float* sXY = smem + W_TOT;
    __shared__ int s_node[NB];
    __shared__ int s_tile;

    const int tid = threadIdx.x;
    const int nt  = g_ntiles;
    const uint32_t sW_u  = smem_u32(sW);
    const uint32_t sXY_u = smem_u32(sXY);

    for (;;) {
        if (tid == 0) s_tile = atomicAdd(&g_tile_ctr, 1);
        __syncthreads();
        const int t = s_tile;
        if (t >= nt) break;

        const int e  = g_tile_e[t];
        const int r0 = g_tile_r0[t];
        const int R  = g_tile_R[t];
        if (tid < R) s_node[tid] = g_perm[r0 + tid];
        __syncthreads();

        // Overlap: W slice (57 KB) + seg0 x staging in one cp.async group
        const float4* Wg = (const float4*)(W + (size_t)e * W_TOT);
        #pragma unroll 2
        for (int i = tid; i < W_TOT / 4; i += NTHREADS)
            cpa16(sW_u + 16u * i, Wg + i);
        stage_x<96, 0>(sXY_u, sXY, x, s_node, R, tid);
        cpa_commit_wait();
        __syncthreads();

        // seg0: mi=96 mo=96 d=1 -> M=64,N=96.  16x16 threads, 4x6 reg tile
        seg_compute<96, 96, 1, 16, 6, 16, 4, 0, 0>(sW, sXY, y, s_node, R, tid);

        // seg1: mi=64 mo=64 d=3 -> M=192,N=64. 16x16 threads, 12x4 reg tile
        stage_x<192, 96>(sXY_u, sXY, x, s_node, R, tid);
        cpa_commit_wait();
        __syncthreads();
        seg_compute<64, 64, 3, 16, 4, 16, 12, 9216, 96>(sW, sXY, y, s_node, R, tid);

        // seg2: mi=32 mo=32 d=5 -> M=320,N=32. 8x32 threads, 10x4 reg tile
        stage_x<160, 288>(sXY_u, sXY, x, s_node, R, tid);
        cpa_commit_wait();
        __syncthreads();
        seg_compute<32, 32, 5, 8, 4, 32, 10, 13312, 288>(sW, sXY, y, s_node, R, tid);
    }
}

// ---------------------------------------------------------------------------
// Launch
// ---------------------------------------------------------------------------
extern "C" void kernel_launch(void* const* d_in, const int* in_sizes, int n_in,
                              void* d_out, int out_size)
{
    const float* W  = (const float*)d_in[0];   // [64, 14336]
    const float* x  = (const float*)d_in[1];   // [16384, 448]
    const void*  ix = d_in[2];                 // [16384] int32 or int64
    float* y = (float*)d_out;                  // [16384, 448]

    cudaFuncSetAttribute(compute_kernel,
                         cudaFuncAttributeMaxDynamicSharedMemorySize, SMEM_BYTES);

    hist_kernel<<<NHB, PTHREADS>>>(ix);
    scan_tiles_kernel<<<1, 64>>>();
    scatter_kernel<<<NHB, PTHREADS>>>(ix);
    compute_kernel<<<GRID_COMPUTE, NTHREADS, SMEM_BYTES>>>(W, x, y);
}

// round 4
// speedup vs baseline: 1.3206x; 1.3206x over previous
#include <cuda_runtime.h>
#include <cstdint>

// Problem constants
#define BATCH    16384
#define IN_SIZE  448
#define OUT_SIZE 448
#define W_TOT    14336
#define NE       64
#define NB       32          // nodes per compute tile
#define NTHREADS 256         // compute kernel
#define PTHREADS 128         // preproc kernels
#define NHB      (BATCH / PTHREADS)   // 128 preproc blocks
#define MAX_TILES 640
#define GRID_COMPUTE 296     // 2 CTAs/SM x 148 SMs

// Device scratch (allocation-free rule)
__device__ int g_hist[NHB][NE];
__device__ int g_base[NHB][NE];
__device__ int g_count[NE];
__device__ int g_offset[NE + 1];
__device__ int g_perm[BATCH];
__device__ int g_ntiles;
__device__ int g_tile_ctr;
__device__ int g_tile_e[MAX_TILES];
__device__ int g_tile_r0[MAX_TILES];
__device__ int g_tile_R[MAX_TILES];

__device__ __forceinline__ int get_idx(const void* p, int b, int is64) {
    if (is64) return (int)((const long long*)p)[b];
    return ((const int*)p)[b];
}

// Block-cooperative dtype detection (int32 vs int64 indices).
__device__ __forceinline__ int detect_is64(const void* idxp, int tid, int* s_flag) {
    if (tid < 32) {
        long long v = ((const long long*)idxp)[tid];
        unsigned ok = __ballot_sync(0xFFFFFFFFu, v >= 0 && v < 64);
        if (tid == 0) *s_flag = (ok == 0xFFFFFFFFu) ? 1 : 0;
    }
    __syncthreads();
    return *s_flag;
}

// ---------------------------------------------------------------------------
// Pass 1: per-block histogram
// ---------------------------------------------------------------------------
__global__ void hist_kernel(const void* idxp) {
    __shared__ int h[NE];
    __shared__ int sflag;
    int tid = threadIdx.x;
    if (tid < NE) h[tid] = 0;
    int is64 = detect_is64(idxp, tid, &sflag);  // contains __syncthreads
    int b = blockIdx.x * PTHREADS + tid;
    int e = get_idx(idxp, b, is64);
    atomicAdd(&h[e], 1);
    __syncthreads();
    if (tid < NE) g_hist[blockIdx.x][tid] = h[tid];
}

// ---------------------------------------------------------------------------
// Pass 2a: per-element exclusive scan over the 128 block-histograms
// grid = NE blocks, 128 threads each
// ---------------------------------------------------------------------------
__global__ void scan_e_kernel() {
    __shared__ int ws[4];
    int e = blockIdx.x;
    int t = threadIdx.x;                  // block index b
    int v = g_hist[t][e];
    int lane = t & 31, w = t >> 5;
    // inclusive warp scan
    int p = v;
    #pragma unroll
    for (int d = 1; d < 32; d <<= 1) {
        int n = __shfl_up_sync(0xFFFFFFFFu, p, d);
        if (lane >= d) p += n;
    }
    if (lane == 31) ws[w] = p;
    __syncthreads();
    if (t == 0) {
        int s = 0;
        #pragma unroll
        for (int i = 0; i < 4; i++) { int x = ws[i]; ws[i] = s; s += x; }
    }
    __syncthreads();
    int excl = p - v + ws[w];
    g_base[t][e] = excl;
    if (t == PTHREADS - 1) g_count[e] = excl + v;
}

// ---------------------------------------------------------------------------
// Pass 2b: offsets + tile list (tiny)
// ---------------------------------------------------------------------------
__global__ void tiles_kernel() {
    __shared__ int cnt[NE], toff[NE];
    int t = threadIdx.x;                  // 64 threads
    cnt[t] = g_count[t];
    __syncthreads();
    if (t == 0) {
        int s = 0, ts = 0;
        for (int i = 0; i < NE; i++) {
            g_offset[i] = s; s += cnt[i];
            toff[i] = ts; ts += (cnt[i] + NB - 1) / NB;
        }
        g_offset[NE] = s;
        g_ntiles = ts;
        g_tile_ctr = 0;
    }
    __syncthreads();
    int c = cnt[t], tb = toff[t], off = g_offset[t];
    for (int i = 0; i * NB < c; i++) {
        g_tile_e[tb + i]  = t;
        g_tile_r0[tb + i] = off + i * NB;
        g_tile_R[tb + i]  = min(NB, c - i * NB);
    }
}

// ---------------------------------------------------------------------------
// Pass 3: scatter (zero global atomics)
// ---------------------------------------------------------------------------
__global__ void scatter_kernel(const void* idxp) {
    __shared__ int h[NE];
    __shared__ int sflag;
    int tid = threadIdx.x;
    if (tid < NE) h[tid] = 0;
    int is64 = detect_is64(idxp, tid, &sflag);
    int b = blockIdx.x * PTHREADS + tid;
    int e = get_idx(idxp, b, is64);
    int rank = atomicAdd(&h[e], 1);       // smem atomic only
    g_perm[g_offset[e] + g_base[blockIdx.x][e] + rank] = b;
}

// ---------------------------------------------------------------------------
// Compute kernel
// ---------------------------------------------------------------------------
// SMEM floats: sW[14336] | A[6272] | B[6144]
#define A_FLOATS 6272
#define B_FLOATS 6144
#define SMEM_FLOATS (W_TOT + A_FLOATS + B_FLOATS)
#define SMEM_BYTES  (SMEM_FLOATS * 4)

__device__ __forceinline__ uint32_t smem_u32(const void* p) {
    uint32_t a;
    asm("{ .reg .u64 t; cvta.to.shared.u64 t, %1; cvt.u32.u64 %0, t; }"
        : "=r"(a) : "l"(p));
    return a;
}
__device__ __forceinline__ void cpa16(uint32_t dst, const void* src) {
    asm volatile("cp.async.cg.shared.global [%0], [%1], 16;\n" :: "r"(dst), "l"(src));
}
__device__ __forceinline__ void cpa4(uint32_t dst, const void* src) {
    asm volatile("cp.async.ca.shared.global [%0], [%1], 4;\n" :: "r"(dst), "l"(src));
}
__device__ __forceinline__ void cpa_commit() {
    asm volatile("cp.async.commit_group;\n" ::: "memory");
}
__device__ __forceinline__ void cpa_wait0() {
    asm volatile("cp.async.wait_group 0;\n" ::: "memory");
}
__device__ __forceinline__ float f4get(const float4& v, int k) {
    return k == 0 ? v.x : k == 1 ? v.y : k == 2 ? v.z : v.w;
}

__global__ void __launch_bounds__(NTHREADS)
compute_kernel(const float* __restrict__ W, const float* __restrict__ x,
               float* __restrict__ y)
{
    extern __shared__ float sm[];
    float* sW = sm;
    float* sA = sm + W_TOT;
    float* sB = sA + A_FLOATS;
    __shared__ int s_node[NB];
    __shared__ int s_tile;

    const int tid = threadIdx.x;
    const int nt  = g_ntiles;
    const uint32_t sW_u = smem_u32(sW);
    const uint32_t sA_u = smem_u32(sA);
    const uint32_t sB_u = smem_u32(sB);

    const int tx16 = tid & 15, ty16 = tid >> 4;   // 16x16 grid (seg0, seg1)
    const int tx8  = tid & 7,  ty8  = tid >> 3;   // 8x32 grid (seg2)

    for (;;) {
        if (tid == 0) s_tile = atomicAdd(&g_tile_ctr, 1);
        __syncthreads();                 // also: prev writeout reads done
        const int t = s_tile;
        if (t >= nt) break;
        const int e  = g_tile_e[t];
        const int r0 = g_tile_r0[t];
        const int R  = g_tile_R[t];
        if (tid < NB) s_node[tid] = (tid < R) ? g_perm[r0 + tid] : 0;
        __syncthreads();
        const int RZ = min(NB, R + 2);

        // ================= stage W + seg0 x (A) + seg1 x transposed (B) =====
        {
            const float4* Wg = (const float4*)(W + (size_t)e * W_TOT);
            #pragma unroll 2
            for (int i = tid; i < W_TOT / 4; i += NTHREADS)
                cpa16(sW_u + 16u * i, Wg + i);
            // seg0 x: [nb][96] float4
            for (int idx = tid; idx < NB * 24; idx += NTHREADS) {
                int nb = idx / 24, o4 = idx - nb * 24;
                if (nb < R)
                    cpa16(sA_u + 4u * (nb * 96 + 4 * o4),
                          x + (size_t)s_node[nb] * IN_SIZE + 4 * o4);
                else if (nb < RZ)
                    *(float4*)(sA + nb * 96 + 4 * o4) = make_float4(0, 0, 0, 0);
            }
            // seg1 x transposed: [nb][m][64] (m=0..2, mi=0..63)
            for (int idx = tid; idx < NB * 192; idx += NTHREADS) {
                int nb = idx / 192, off = idx - nb * 192;
                if (nb < R) {
                    int mi = off / 3, m = off - 3 * mi;
                    cpa4(sB_u + 4u * (nb * 192 + m * 64 + mi),
                         x + (size_t)s_node[nb] * IN_SIZE + 96 + off);
                } else if (nb < RZ)
                    sB[nb * 192 + off] = 0.f;
            }
            cpa_commit();
            cpa_wait0();
        }
        __syncthreads();

        // ================= seg0: mi=96 mo=96 d=1 (M=32,N=96) ===============
        // cols: 2*tx16 + 32*p + q (p=0..2, q=0..1); rows: 2*ty16 + a
        {
            const bool act = (2 * ty16) < R;
            float acc[2][6];
            #pragma unroll
            for (int a = 0; a < 2; a++)
                #pragma unroll
                for (int j = 0; j < 6; j++) acc[a][j] = 0.f;
            if (act) {
                const float* xb0 = sA + (2 * ty16) * 96;
                const float* xb1 = sA + (2 * ty16 + 1) * 96;
                #pragma unroll 2
                for (int k = 0; k < 96; k += 4) {
                    float4 xv0 = *(const float4*)(xb0 + k);
                    float4 xv1 = *(const float4*)(xb1 + k);
                    #pragma unroll
                    for (int kk = 0; kk < 4; kk++) {
                        const float* wr = sW + (k + kk) * 96 + 2 * tx16;
                        float2 w0 = *(const float2*)(wr);
                        float2 w1 = *(const float2*)(wr + 32);
                        float2 w2 = *(const float2*)(wr + 64);
                        float xa = f4get(xv0, kk), xbv = f4get(xv1, kk);
                        acc[0][0] = fmaf(xa, w0.x, acc[0][0]);
                        acc[0][1] = fmaf(xa, w0.y, acc[0][1]);
                        acc[0][2] = fmaf(xa, w1.x, acc[0][2]);
                        acc[0][3] = fmaf(xa, w1.y, acc[0][3]);
                        acc[0][4] = fmaf(xa, w2.x, acc[0][4]);
                        acc[0][5] = fmaf(xa, w2.y, acc[0][5]);
                        acc[1][0] = fmaf(xbv, w0.x, acc[1][0]);
                        acc[1][1] = fmaf(xbv, w0.y, acc[1][1]);
                        acc[1][2] = fmaf(xbv, w1.x, acc[1][2]);
                        acc[1][3] = fmaf(xbv, w1.y, acc[1][3]);
                        acc[1][4] = fmaf(xbv, w2.x, acc[1][4]);
                        acc[1][5] = fmaf(xbv, w2.y, acc[1][5]);
                    }
                }
            }
            __syncthreads();                       // x reads done
            if (act) {
                #pragma unroll
                for (int a = 0; a < 2; a++) {
                    float* row = sA + (2 * ty16 + a) * 100 + 2 * tx16;
                    row[0]  = acc[a][0]; row[1]  = acc[a][1];
                    row[32] = acc[a][2]; row[33] = acc[a][3];
                    row[64] = acc[a][4]; row[65] = acc[a][5];
                }
            }
            __syncthreads();
            for (int idx = tid; idx < R * 24; idx += NTHREADS) {
                int nb = idx / 24, o4 = idx - nb * 24;
                *(float4*)(y + (size_t)s_node[nb] * OUT_SIZE + 4 * o4) =
                    *(const float4*)(sA + nb * 100 + 4 * o4);
            }
            // no sync: seg1 touches only sB/sW; sA next written after a sync
        }

        // ================= seg1: mi=64 mo=64 d=3 (M=96,N=64) ===============
        // cols: 4*tx16 + j; rows r=6*ty16+a -> nb=2*ty16+a/3, m=a%3
        {
            const int nb0 = 2 * ty16;
            const bool act = nb0 < R;
            float acc[6][4];
            #pragma unroll
            for (int a = 0; a < 6; a++)
                #pragma unroll
                for (int j = 0; j < 4; j++) acc[a][j] = 0.f;
            if (act) {
                const float* xb = sB + nb0 * 192;
                #pragma unroll 2
                for (int k = 0; k < 64; k += 4) {
                    float4 xv[6];
                    #pragma unroll
                    for (int a = 0; a < 6; a++) {
                        int boff = (a < 3) ? a * 64 : 192 + (a - 3) * 64;
                        xv[a] = *(const float4*)(xb + boff + k);
                    }
                    #pragma unroll
                    for (int kk = 0; kk < 4; kk++) {
                        float4 wv = *(const float4*)(sW + 9216 + (k + kk) * 64 + 4 * tx16);
                        #pragma unroll
                        for (int a = 0; a < 6; a++) {
                            float xa = f4get(xv[a], kk);
                            acc[a][0] = fmaf(xa, wv.x, acc[a][0]);
                            acc[a][1] = fmaf(xa, wv.y, acc[a][1]);
                            acc[a][2] = fmaf(xa, wv.z, acc[a][2]);
                            acc[a][3] = fmaf(xa, wv.w, acc[a][3]);
                        }
                    }
                }
            }
            __syncthreads();     // seg0 writeout A-reads + seg1 B-reads done
            if (act) {
                #pragma unroll
                for (int a = 0; a < 6; a++) {
                    int nb = nb0 + a / 3, m = a - 3 * (a / 3);
                    float* base = sA + nb * 196 + (4 * tx16) * 3 + m;
                    base[0] = acc[a][0]; base[3] = acc[a][1];
                    base[6] = acc[a][2]; base[9] = acc[a][3];
                }
            }
            // stage seg2 x transposed into sB: [nb][m][32] (m=0..4, mi=0..31)
            for (int idx = tid; idx < NB * 160; idx += NTHREADS) {
                int nb = idx / 160, off = idx - nb * 160;
                if (nb < R) {
                    int mi = off / 5, m = off - 5 * mi;
                    cpa4(sB_u + 4u * (nb * 160 + m * 32 + mi),
                         x + (size_t)s_node[nb] * IN_SIZE + 288 + off);
                } else if (nb < RZ)
                    sB[nb * 160 + off] = 0.f;
            }
            cpa_commit();
            __syncthreads();     // y1 staged in sA complete
            for (int idx = tid; idx < R * 48; idx += NTHREADS) {
                int nb = idx / 48, o4 = idx - nb * 48;
                *(float4*)(y + (size_t)s_node[nb] * OUT_SIZE + 96 + 4 * o4) =
                    *(const float4*)(sA + nb * 196 + 4 * o4);
            }
            cpa_wait0();
            __syncthreads();     // seg2 x in sB visible to all
        }

        // ================= seg2: mi=32 mo=32 d=5 (M=160,N=32) ==============
        // cols: 4*tx8 + j; rows r=5*ty8+a -> nb=ty8, m=a
        {
            const bool act = ty8 < R;
            float acc[5][4];
            #pragma unroll
            for (int a = 0; a < 5; a++)
                #pragma unroll
                for (int j = 0; j < 4; j++) acc[a][j] = 0.f;
            if (act) {
                const float* xb = sB + ty8 * 160;
                #pragma unroll 2
                for (int k = 0; k < 32; k += 4) {
                    float4 xv[5];
                    #pragma unroll
                    for (int a = 0; a < 5; a++)
                        xv[a] = *(const float4*)(xb + a * 32 + k);
                    #pragma unroll
                    for (int kk = 0; kk < 4; kk++) {
                        float4 wv = *(const float4*)(sW + 13312 + (k + kk) * 32 + 4 * tx8);
                        #pragma unroll
                        for (int a = 0; a < 5; a++) {
                            float xa = f4get(xv[a], kk);
                            acc[a][0] = fmaf(xa, wv.x, acc[a][0]);
                            acc[a][1] = fmaf(xa, wv.y, acc[a][1]);
                            acc[a][2] = fmaf(xa, wv.z, acc[a][2]);
                            acc[a][3] = fmaf(xa, wv.w, acc[a][3]);
                        }
                    }
                }
            }
            __syncthreads();     // writeout1 A-reads + seg2 B-reads done
            if (act) {
                #pragma unroll
                for (int a = 0; a < 5; a++) {
                    float* base = sA + ty8 * 164 + (4 * tx8) * 5 + a;
                    base[0]  = acc[a][0]; base[5]  = acc[a][1];
                    base[10] = acc[a][2]; base[15] = acc[a][3];
                }
            }
            __syncthreads();
            for (int idx = tid; idx < R * 40; idx += NTHREADS) {
                int nb = idx / 40, o4 = idx - nb * 40;
                *(float4*)(y + (size_t)s_node[nb] * OUT_SIZE + 288 + 4 * o4) =
                    *(const float4*)(sA + nb * 164 + 4 * o4);
            }
            // loop-top sync guards sA/sB/sW reuse
        }
    }
}

// ---------------------------------------------------------------------------
// Launch
// ---------------------------------------------------------------------------
extern "C" void kernel_launch(void* const* d_in, const int* in_sizes, int n_in,
                              void* d_out, int out_size)
{
    const float* W  = (const float*)d_in[0];   // [64, 14336]
    const float* x  = (const float*)d_in[1];   // [16384, 448]
    const void*  ix = d_in[2];                 // [16384] int32 or int64
    float* y = (float*)d_out;                  // [16384, 448]

    cudaFuncSetAttribute(compute_kernel,
                         cudaFuncAttributeMaxDynamicSharedMemorySize, SMEM_BYTES);

    hist_kernel<<<NHB, PTHREADS>>>(ix);
    scan_e_kernel<<<NE, PTHREADS>>>();
    tiles_kernel<<<1, 64>>>();
    scatter_kernel<<<NHB, PTHREADS>>>(ix);
    compute_kernel<<<GRID_COMPUTE, NTHREADS, SMEM_BYTES>>>(W, x, y);
}

// round 7
// speedup vs baseline: 1.4184x; 1.0741x over previous
#include <cuda_runtime.h>
#include <cstdint>

// Problem constants
#define BATCH    16384
#define IN_SIZE  448
#define OUT_SIZE 448
#define W_TOT    14336
#define NE       64
#define NB       64
#define NTHREADS 256
#define PTHREADS 128
#define NHB      (BATCH / PTHREADS)   // 128
#define MAX_TILES 448
#define GRID_COMPUTE 296

// Device scratch
__device__ int g_hist[NHB][NE];
__device__ int g_perm[BATCH];
__device__ int g_ntiles;
__device__ int g_tile_ctr;
__device__ int g_tile_e[MAX_TILES];
__device__ int g_tile_r0[MAX_TILES];
__device__ int g_tile_R[MAX_TILES];

__device__ __forceinline__ int get_idx(const void* p, int b, int is64) {
    if (is64) return (int)((const long long*)p)[b];
    return ((const int*)p)[b];
}
__device__ __forceinline__ int detect_is64(const void* idxp, int tid, int* s_flag) {
    if (tid < 32) {
        long long v = ((const long long*)idxp)[tid];
        unsigned ok = __ballot_sync(0xFFFFFFFFu, v >= 0 && v < 64);
        if (tid == 0) *s_flag = (ok == 0xFFFFFFFFu) ? 1 : 0;
    }
    __syncthreads();
    return *s_flag;
}

// ---------------------------------------------------------------------------
// K1: per-block histogram (1 node / thread)
// ---------------------------------------------------------------------------
__global__ void hist_kernel(const void* idxp) {
    __shared__ int h[NE];
    __shared__ int sflag;
    int tid = threadIdx.x;
    if (tid < NE) h[tid] = 0;
    int is64 = detect_is64(idxp, tid, &sflag);
    int b = blockIdx.x * PTHREADS + tid;
    int e = get_idx(idxp, b, is64);
    atomicAdd(&h[e], 1);
    __syncthreads();
    if (tid < NE) g_hist[blockIdx.x][tid] = h[tid];
}

// ---------------------------------------------------------------------------
// K2: fused scan + scatter + tile-list (grid NHB)
// ---------------------------------------------------------------------------
__global__ void finish_kernel(const void* idxp) {
    __shared__ int preS[NE], totS[NE], offS[NE];
    __shared__ int sflag;
    int t = threadIdx.x;
    int b = blockIdx.x;
    int is64 = detect_is64(idxp, t, &sflag);
    if (t < NE) {
        int pre = 0, tot = 0;
        #pragma unroll 8
        for (int bb = 0; bb < NHB; bb++) {
            int v = g_hist[bb][t];
            tot += v;
            if (bb < b) pre += v;
        }
        preS[t] = pre; totS[t] = tot;
    }
    __syncthreads();
    if (t == 0) {
        int s = 0;
        for (int e2 = 0; e2 < NE; e2++) { offS[e2] = s; s += totS[e2]; }
    }
    __syncthreads();
    int my = b * PTHREADS + t;
    int e = get_idx(idxp, my, is64);
    int rank = atomicAdd(&preS[e], 1);
    g_perm[offS[e] + rank] = my;

    if (b == 0 && t == 0) {
        // Tile list: full tiles first, partials at the end (cheap stragglers)
        int ts = 0;
        for (int e2 = 0; e2 < NE; e2++) {
            int c = totS[e2], o = offS[e2], nf = c >> 6;
            for (int i = 0; i < nf; i++) {
                g_tile_e[ts] = e2; g_tile_r0[ts] = o + (i << 6); g_tile_R[ts] = NB; ts++;
            }
        }
        for (int e2 = 0; e2 < NE; e2++) {
            int c = totS[e2], o = offS[e2], nf = c >> 6, rem = c & 63;
            if (rem) {
                g_tile_e[ts] = e2; g_tile_r0[ts] = o + (nf << 6); g_tile_R[ts] = rem; ts++;
            }
        }
        g_ntiles = ts;
        g_tile_ctr = 0;
    }
}

// ---------------------------------------------------------------------------
// Compute kernel
// ---------------------------------------------------------------------------
// SMEM floats: sW[14336] | sX[64*192]
#define SX_FLOATS (NB * 192)
#define SMEM_BYTES ((W_TOT + SX_FLOATS) * 4)

__device__ __forceinline__ uint32_t smem_u32(const void* p) {
    uint32_t a;
    asm("{ .reg .u64 t; cvta.to.shared.u64 t, %1; cvt.u32.u64 %0, t; }"
        : "=r"(a) : "l"(p));
    return a;
}
__device__ __forceinline__ void cpa16(uint32_t dst, const void* src) {
    asm volatile("cp.async.cg.shared.global [%0], [%1], 16;\n" :: "r"(dst), "l"(src));
}
__device__ __forceinline__ void cpa_commit() {
    asm volatile("cp.async.commit_group;\n" ::: "memory");
}
__device__ __forceinline__ void cpa_wait0() {
    asm volatile("cp.async.wait_group 0;\n" ::: "memory");
}
__device__ __forceinline__ float f4get(const float4& v, int k) {
    return k == 0 ? v.x : k == 1 ? v.y : k == 2 ? v.z : v.w;
}

__global__ void __launch_bounds__(NTHREADS)
compute_kernel(const float* __restrict__ W, const float* __restrict__ x,
               float* __restrict__ y)
{
    extern __shared__ float sm[];
    float* sW = sm;
    float* sX = sm + W_TOT;
    __shared__ int s_node[NB];
    __shared__ int s_tile;

    const int tid = threadIdx.x;
    const uint32_t sW_u = smem_u32(sW);
    const uint32_t sX_u = smem_u32(sX);

    const int nt = g_ntiles;
    const int tx16 = tid & 15, ty16 = tid >> 4;   // seg0/seg1 grids
    const int tx8  = tid & 7,  ty8  = tid >> 3;   // seg2 grid

    // Bounded persistent loop: identical behavior when healthy; guarantees
    // termination (wrong-answer, not hang) if tile metadata were ever bad.
    for (int iter = 0; iter < MAX_TILES + 8; iter++) {
        if (tid == 0) s_tile = atomicAdd(&g_tile_ctr, 1);
        __syncthreads();                       // also guards sW/sX reuse
        const int t = s_tile;
        if (t >= nt) break;
        const int e  = g_tile_e[t];
        const int r0 = g_tile_r0[t];
        const int R  = g_tile_R[t];
        if (tid < NB) s_node[tid] = g_perm[r0 + min(tid, R - 1)];
        __syncthreads();

        // Stage W (57 KB) + seg0 x in one cp.async group
        {
            const float4* Wg = (const float4*)(W + (size_t)e * W_TOT);
            #pragma unroll 2
            for (int i = tid; i < W_TOT / 4; i += NTHREADS)
                cpa16(sW_u + 16u * i, Wg + i);
            for (int i = tid; i < NB * 24; i += NTHREADS) {
                int nb = i / 24, o = i - nb * 24;
                cpa16(sX_u + 4u * (nb * 96 + 4 * o),
                      x + (size_t)s_node[nb] * IN_SIZE + 4 * o);
            }
            cpa_commit();
            cpa_wait0();
        }
        __syncthreads();

        // ============ seg0: mi=96 mo=96 d=1 ============
        // thread: nodes 4*ty16+a, cols {4tx..4tx+3} u {64+2tx, 64+2tx+1}
        {
            const int n0 = 4 * ty16;
            const bool act = n0 < R;
            float acc[4][6];
            #pragma unroll
            for (int a = 0; a < 4; a++)
                #pragma unroll
                for (int j = 0; j < 6; j++) acc[a][j] = 0.f;
            if (act) {
                #pragma unroll 2
                for (int g = 0; g < 24; g++) {
                    float4 xq[4];
                    #pragma unroll
                    for (int a = 0; a < 4; a++)
                        xq[a] = *(const float4*)(sX + (n0 + a) * 96 + 4 * g);
                    #pragma unroll
                    for (int kk = 0; kk < 4; kk++) {
                        const float* wr = sW + (4 * g + kk) * 96;
                        float4 w0 = *(const float4*)(wr + 4 * tx16);
                        float2 w1 = *(const float2*)(wr + 64 + 2 * tx16);
                        #pragma unroll
                        for (int a = 0; a < 4; a++) {
                            float xs = f4get(xq[a], kk);
                            acc[a][0] = fmaf(xs, w0.x, acc[a][0]);
                            acc[a][1] = fmaf(xs, w0.y, acc[a][1]);
                            acc[a][2] = fmaf(xs, w0.z, acc[a][2]);
                            acc[a][3] = fmaf(xs, w0.w, acc[a][3]);
                            acc[a][4] = fmaf(xs, w1.x, acc[a][4]);
                            acc[a][5] = fmaf(xs, w1.y, acc[a][5]);
                        }
                    }
                }
            }
            __syncthreads();   // sX reads done -> restage
            // stage seg1 x: [nb][192] natural
            for (int i = tid; i < NB * 48; i += NTHREADS) {
                int nb = i / 48, o = i - nb * 48;
                cpa16(sX_u + 4u * (nb * 192 + 4 * o),
                      x + (size_t)s_node[nb] * IN_SIZE + 96 + 4 * o);
            }
            cpa_commit();
            if (act) {
                #pragma unroll
                for (int a = 0; a < 4; a++) {
                    if (n0 + a < R) {
                        float* yp = y + (size_t)s_node[n0 + a] * OUT_SIZE;
                        *(float4*)(yp + 4 * tx16) =
                            make_float4(acc[a][0], acc[a][1], acc[a][2], acc[a][3]);
                        *(float2*)(yp + 64 + 2 * tx16) =
                            make_float2(acc[a][4], acc[a][5]);
                    }
                }
            }
            cpa_wait0();
            __syncthreads();
        }

        // ============ seg1: mi=64 mo=64 d=3 ============
        // thread: nodes 4*ty16+a, m=0..2, cols 4tx..4tx+3
        {
            const int n0 = 4 * ty16;
            const bool act = n0 < R;
            float acc[4][3][4];
            #pragma unroll
            for (int a = 0; a < 4; a++)
                #pragma unroll
                for (int m = 0; m < 3; m++)
                    #pragma unroll
                    for (int c = 0; c < 4; c++) acc[a][m][c] = 0.f;
            if (act) {
                #pragma unroll 2
                for (int g = 0; g < 16; g++) {
                    float4 wv[4];
                    #pragma unroll
                    for (int kk = 0; kk < 4; kk++)
                        wv[kk] = *(const float4*)(sW + 9216 + (4 * g + kk) * 64 + 4 * tx16);
                    #pragma unroll
                    for (int a = 0; a < 4; a++) {
                        const float* xr = sX + (n0 + a) * 192 + 12 * g;
                        float xf[12];
                        *(float4*)(xf + 0) = *(const float4*)(xr + 0);
                        *(float4*)(xf + 4) = *(const float4*)(xr + 4);
                        *(float4*)(xf + 8) = *(const float4*)(xr + 8);
                        #pragma unroll
                        for (int kk = 0; kk < 4; kk++) {
                            #pragma unroll
                            for (int m = 0; m < 3; m++) {
                                float xs = xf[kk * 3 + m];
                                acc[a][m][0] = fmaf(xs, wv[kk].x, acc[a][m][0]);
                                acc[a][m][1] = fmaf(xs, wv[kk].y, acc[a][m][1]);
                                acc[a][m][2] = fmaf(xs, wv[kk].z, acc[a][m][2]);
                                acc[a][m][3] = fmaf(xs, wv[kk].w, acc[a][m][3]);
                            }
                        }
                    }
                }
            }
            __syncthreads();   // sX reads done -> restage
            // stage seg2 x: [nb][160] natural
            for (int i = tid; i < NB * 40; i += NTHREADS) {
                int nb = i / 40, o = i - nb * 40;
                cpa16(sX_u + 4u * (nb * 160 + 4 * o),
                      x + (size_t)s_node[nb] * IN_SIZE + 288 + 4 * o);
            }
            cpa_commit();
            if (act) {
                #pragma unroll
                for (int a = 0; a < 4; a++) {
                    if (n0 + a < R) {
                        float* yp = y + (size_t)s_node[n0 + a] * OUT_SIZE + 96 + 12 * tx16;
                        *(float4*)(yp + 0) = make_float4(acc[a][0][0], acc[a][1][0],
                                                         acc[a][2][0], acc[a][0][1]);
                        *(float4*)(yp + 4) = make_float4(acc[a][1][1], acc[a][2][1],
                                                         acc[a][0][2], acc[a][1][2]);
                        *(float4*)(yp + 8) = make_float4(acc[a][2][2], acc[a][0][3],
                                                         acc[a][1][3], acc[a][2][3]);
                    }
                }
            }
            cpa_wait0();
            __syncthreads();
        }

        // ============ seg2: mi=32 mo=32 d=5 ============
        // thread: nodes 2*ty8+a, m=0..4, cols 4tx8..4tx8+3
        {
            const int n0 = 2 * ty8;
            const bool act = n0 < R;
            float acc[2][5][4];
            #pragma unroll
            for (int a = 0; a < 2; a++)
                #pragma unroll
                for (int m = 0; m < 5; m++)
                    #pragma unroll
                    for (int c = 0; c < 4; c++) acc[a][m][c] = 0.f;
            if (act) {
                #pragma unroll 2
                for (int g = 0; g < 8; g++) {
                    float4 wv[4];
                    #pragma unroll
                    for (int kk = 0; kk < 4; kk++)
                        wv[kk] = *(const float4*)(sW + 13312 + (4 * g + kk) * 32 + 4 * tx8);
                    #pragma unroll
                    for (int a = 0; a < 2; a++) {
                        const float* xr = sX + (n0 + a) * 160 + 20 * g;
                        float xf[20];
                        *(float4*)(xf + 0)  = *(const float4*)(xr + 0);
                        *(float4*)(xf + 4)  = *(const float4*)(xr + 4);
                        *(float4*)(xf + 8)  = *(const float4*)(xr + 8);
                        *(float4*)(xf + 12) = *(const float4*)(xr + 12);
                        *(float4*)(xf + 16) = *(const float4*)(xr + 16);
                        #pragma unroll
                        for (int kk = 0; kk < 4; kk++) {
                            #pragma unroll
                            for (int m = 0; m < 5; m++) {
                                float xs = xf[kk * 5 + m];
                                acc[a][m][0] = fmaf(xs, wv[kk].x, acc[a][m][0]);
                                acc[a][m][1] = fmaf(xs, wv[kk].y, acc[a][m][1]);
                                acc[a][m][2] = fmaf(xs, wv[kk].z, acc[a][m][2]);
                                acc[a][m][3] = fmaf(xs, wv[kk].w, acc[a][m][3]);
                            }
                        }
                    }
                }
                #pragma unroll
                for (int a = 0; a < 2; a++) {
                    if (n0 + a < R) {
                        float* yp = y + (size_t)s_node[n0 + a] * OUT_SIZE + 288 + 20 * tx8;
                        *(float4*)(yp + 0)  = make_float4(acc[a][0][0], acc[a][1][0],
                                                          acc[a][2][0], acc[a][3][0]);
                        *(float4*)(yp + 4)  = make_float4(acc[a][4][0], acc[a][0][1],
                                                          acc[a][1][1], acc[a][2][1]);
                        *(float4*)(yp + 8)  = make_float4(acc[a][3][1], acc[a][4][1],
                                                          acc[a][0][2], acc[a][1][2]);
                        *(float4*)(yp + 12) = make_float4(acc[a][2][2], acc[a][3][2],
                                                          acc[a][4][2], acc[a][0][3]);
                        *(float4*)(yp + 16) = make_float4(acc[a][1][3], acc[a][2][3],
                                                          acc[a][3][3], acc[a][4][3]);
                    }
                }
            }
            // loop-top __syncthreads() guards sW/sX reuse for next tile
        }
    }
}

// ---------------------------------------------------------------------------
// Launch
// ---------------------------------------------------------------------------
extern "C" void kernel_launch(void* const* d_in, const int* in_sizes, int n_in,
                              void* d_out, int out_size)
{
    const float* W  = (const float*)d_in[0];   // [64, 14336]
    const float* x  = (const float*)d_in[1];   // [16384, 448]
    const void*  ix = d_in[2];                 // [16384] int32 or int64
    float* y = (float*)d_out;                  // [16384, 448]

    cudaFuncSetAttribute(compute_kernel,
                         cudaFuncAttributeMaxDynamicSharedMemorySize, SMEM_BYTES);

    hist_kernel<<<NHB, PTHREADS>>>(ix);
    finish_kernel<<<NHB, PTHREADS>>>(ix);
    compute_kernel<<<GRID_COMPUTE, NTHREADS, SMEM_BYTES>>>(W, x, y);
}